// round 5
// baseline (speedup 1.0000x reference)
#include <cuda_runtime.h>
#include <cuda_fp16.h>
#include <cstdint>

// out[M,11008] = x[M,4096] @ dequant(qweight) + bias
// fp16 mma.sync.m16n8k16 + ldmatrix + cp.async; 3-stage mbarrier pipeline.

#define KDIM    4096
#define NDIM    11008
#define NPACK   1376
#define BM      128
#define BN      128
#define BK      64
#define NCHUNK  64
#define MAXM    2048
#define A_BYTES 16384                  // 128 rows x 64 fp16 (128B rows, SW128)
#define B_BYTES 16384                  // 2 subtiles [64k][64n] fp16 (8KB each)
#define STAGE   (A_BYTES + B_BYTES)    // 32768
#define NSTAGE  3
#define SMEM_DYN (NSTAGE*STAGE + 1024)

__device__ __half x16g[(size_t)MAXM * KDIM];

__device__ __forceinline__ uint32_t smem_u32(const void* p) {
    uint32_t a;
    asm("{ .reg .u64 t; cvta.to.shared.u64 t, %1; cvt.u32.u64 %0, t; }" : "=r"(a) : "l"(p));
    return a;
}
__device__ __forceinline__ uint32_t sw128(uint32_t o) { return o ^ ((o >> 3) & 0x70); }

#define LDSM_X4(r0,r1,r2,r3,addr) \
    asm volatile("ldmatrix.sync.aligned.m8n8.x4.shared.b16 {%0,%1,%2,%3}, [%4];" \
        : "=r"(r0),"=r"(r1),"=r"(r2),"=r"(r3) : "r"(addr))
#define LDSM_X4_T(r0,r1,r2,r3,addr) \
    asm volatile("ldmatrix.sync.aligned.m8n8.x4.trans.shared.b16 {%0,%1,%2,%3}, [%4];" \
        : "=r"(r0),"=r"(r1),"=r"(r2),"=r"(r3) : "r"(addr))

__device__ __forceinline__ void mma16816(float* d, const uint32_t* a,
                                         uint32_t b0, uint32_t b1) {
    asm volatile(
        "mma.sync.aligned.m16n8k16.row.col.f32.f16.f16.f32 "
        "{%0,%1,%2,%3}, {%4,%5,%6,%7}, {%8,%9}, {%0,%1,%2,%3};"
        : "+f"(d[0]), "+f"(d[1]), "+f"(d[2]), "+f"(d[3])
        : "r"(a[0]), "r"(a[1]), "r"(a[2]), "r"(a[3]), "r"(b0), "r"(b1));
}
__device__ __forceinline__ void cp16(uint32_t saddr, const void* g) {
    asm volatile("cp.async.cg.shared.global [%0], [%1], 16;" :: "r"(saddr), "l"(g));
}
__device__ __forceinline__ void mbar_init(uint32_t a, uint32_t c) {
    asm volatile("mbarrier.init.shared.b64 [%0], %1;" :: "r"(a), "r"(c) : "memory");
}
__device__ __forceinline__ void mbar_arrive(uint32_t a) {
    asm volatile("mbarrier.arrive.shared.b64 _, [%0];" :: "r"(a) : "memory");
}
__device__ __forceinline__ void cp_arrive(uint32_t a) {
    // default (inc) variant: pending++ at issue, arrive at async completion -> net
    // gates phase completion on this thread's cp.asyncs without changing count.
    asm volatile("cp.async.mbarrier.arrive.shared.b64 [%0];" :: "r"(a) : "memory");
}
__device__ __forceinline__ void mbar_wait(uint32_t a, uint32_t ph) {
    asm volatile(
        "{\n\t.reg .pred P;\n\t"
        "WL%=:\n\t"
        "mbarrier.try_wait.parity.acquire.cta.shared::cta.b64 P, [%0], %1, 0x989680;\n\t"
        "@P bra WD%=;\n\t"
        "bra WL%=;\n\t"
        "WD%=:\n\t}"
        :: "r"(a), "r"(ph) : "memory");
}

// ---------------- prepass: x fp32 -> fp16 (rows >= M zero-filled) ----------------
__global__ __launch_bounds__(256) void cvt_x(const float* __restrict__ x, int M) {
    const size_t e = ((size_t)blockIdx.x * 256 + threadIdx.x) * 8;
    if (e >= (size_t)MAXM * KDIM) return;
    const int row = (int)(e >> 12);
    uint4 v;
    if (row < M) {
        const float4 f0 = reinterpret_cast<const float4*>(x + e)[0];
        const float4 f1 = reinterpret_cast<const float4*>(x + e)[1];
        __half2 p0 = __floats2half2_rn(f0.x, f0.y);
        __half2 p1 = __floats2half2_rn(f0.z, f0.w);
        __half2 p2 = __floats2half2_rn(f1.x, f1.y);
        __half2 p3 = __floats2half2_rn(f1.z, f1.w);
        v.x = *reinterpret_cast<uint32_t*>(&p0);
        v.y = *reinterpret_cast<uint32_t*>(&p1);
        v.z = *reinterpret_cast<uint32_t*>(&p2);
        v.w = *reinterpret_cast<uint32_t*>(&p3);
    } else v = make_uint4(0, 0, 0, 0);
    *reinterpret_cast<uint4*>(x16g + e) = v;
}

// ---------------- main GEMM ----------------
__global__ __launch_bounds__(256, 2) void qlin_f16(
    const int*   __restrict__ qw,
    const int*   __restrict__ qz,
    const float* __restrict__ sc,
    const float* __restrict__ bias,
    float*       __restrict__ out,
    int M)
{
    extern __shared__ char smem_raw[];
    __shared__ __align__(8) uint64_t bars[2 * NSTAGE];   // full[0..2], empty[3..5]

    const uint32_t sb    = (smem_u32(smem_raw) + 1023) & ~1023u;
    const uint32_t barsA = smem_u32(bars);

    const int tid  = threadIdx.x;
    const int lane = tid & 31;
    const int wid  = tid >> 5;
    const int wm   = wid >> 1;
    const int wn   = wid & 1;
    const int m0   = blockIdx.y * BM;
    const int n0   = blockIdx.x * BN;

    if (tid == 0) {
        #pragma unroll
        for (int s = 0; s < NSTAGE; s++) {
            mbar_init(barsA + s * 8, 256);                 // full: 256 STS arrivals (+cp inc/dec)
            mbar_init(barsA + (NSTAGE + s) * 8, 256);      // empty: 256 consumer arrivals
        }
    }
    __syncthreads();

    float acc[2][8][4];
    #pragma unroll
    for (int im = 0; im < 2; im++)
        #pragma unroll
        for (int jn = 0; jn < 8; jn++)
            #pragma unroll
            for (int r = 0; r < 4; r++) acc[im][jn][r] = 0.f;

    // ---- B dequant coords ----
    const int nb = tid & 15;
    const int kq = tid >> 4;
    const size_t nbG = (size_t)(n0 >> 3) + nb;
    __half2 zc[4], s2[4];
    int qreg[4];

    auto refresh_group = [&](int g) {
        const uint32_t zq = (uint32_t)qz[(size_t)g * NPACK + nbG];
        #pragma unroll
        for (int j = 0; j < 4; j++) {
            uint32_t p = ((zq >> (4 * j)) & 0x000F000Fu) | 0x64006400u;
            zc[j] = *reinterpret_cast<__half2*>(&p);
        }
        const float4* sp = reinterpret_cast<const float4*>(
            sc + (size_t)g * NDIM + n0 + nb * 8);
        const float4 sa = sp[0], sbv = sp[1];
        s2[0] = __floats2half2_rn(sa.x, sbv.x);
        s2[1] = __floats2half2_rn(sa.y, sbv.y);
        s2[2] = __floats2half2_rn(sa.z, sbv.z);
        s2[3] = __floats2half2_rn(sa.w, sbv.w);
    };
    auto ldgQ = [&](int t) {
        #pragma unroll
        for (int i = 0; i < 4; i++)
            qreg[i] = qw[(size_t)(t * BK + kq + 16 * i) * NPACK + nbG];
    };

    // produce chunk T into stage s (uses qreg preloaded for T; prefetches T+1)
    auto produce = [&](int T, int s) {
        const uint32_t stg  = sb + s * STAGE;
        const uint32_t full = barsA + s * 8;
        if ((T & 1) == 0) refresh_group(T >> 1);
        // A: 4 cp.async 16B per thread
        {
            const __half* src = x16g + (size_t)m0 * KDIM + T * BK;
            #pragma unroll
            for (int p = 0; p < 4; p++) {
                const int c = tid + p * 256;
                const int row = c >> 3, kc = c & 7;
                cp16(stg + sw128((uint32_t)(row * 128 + kc * 16)),
                     src + (size_t)row * KDIM + kc * 8);
            }
            cp_arrive(full);
        }
        // B dequant -> STS
        {
            char* Bsub = smem_raw + (stg + A_BYTES - smem_u32(smem_raw)) + (nb >> 3) * 8192;
            const uint32_t cb = (uint32_t)((nb & 7) * 16);
            #pragma unroll
            for (int i = 0; i < 4; i++) {
                const int k = kq + 16 * i;
                const uint32_t q = (uint32_t)qreg[i];
                uint32_t w[4];
                #pragma unroll
                for (int j = 0; j < 4; j++) {
                    uint32_t p = ((q >> (4 * j)) & 0x000F000Fu) | 0x64006400u;
                    __half2 hv = __hmul2(__hsub2(*reinterpret_cast<__half2*>(&p), zc[j]), s2[j]);
                    w[j] = *reinterpret_cast<uint32_t*>(&hv);
                }
                uint4 v;
                v.x = __byte_perm(w[0], w[1], 0x5410);
                v.y = __byte_perm(w[2], w[3], 0x5410);
                v.z = __byte_perm(w[0], w[1], 0x7632);
                v.w = __byte_perm(w[2], w[3], 0x7632);
                *reinterpret_cast<uint4*>(Bsub + sw128((uint32_t)(k * 128) + cb)) = v;
            }
        }
        if (T + 1 < NCHUNK) ldgQ(T + 1);
        mbar_arrive(full);
    };

    const int lr = lane & 15, lc = lane >> 4;
    auto compute = [&](int s) {
        const uint32_t aB = sb + s * STAGE;
        const uint32_t bB = aB + A_BYTES + wn * 8192;
        #pragma unroll
        for (int ks = 0; ks < 4; ks++) {
            uint32_t a[2][4];
            #pragma unroll
            for (int im = 0; im < 2; im++) {
                const uint32_t addr = aB + sw128(
                    (uint32_t)((wm * 32 + im * 16 + lr) * 128 + ks * 32 + lc * 16));
                LDSM_X4(a[im][0], a[im][1], a[im][2], a[im][3], addr);
            }
            #pragma unroll
            for (int jn = 0; jn < 4; jn++) {
                uint32_t b0, b1, b2, b3;
                const uint32_t addr = bB + sw128(
                    (uint32_t)((ks * 16 + lr) * 128 + jn * 32 + lc * 16));
                LDSM_X4_T(b0, b1, b2, b3, addr);
                #pragma unroll
                for (int im = 0; im < 2; im++) {
                    mma16816(acc[im][2 * jn],     a[im], b0, b1);
                    mma16816(acc[im][2 * jn + 1], a[im], b2, b3);
                }
            }
        }
    };

    // ---- prologue: fill stages 0 and 1 (fresh stages, no empty-wait) ----
    ldgQ(0);
    produce(0, 0);
    produce(1, 1);

    // ---- main loop with parity cursors (scalar bitmasks, no arrays) ----
    uint32_t pf = 0;        // full parities, bit s
    uint32_t pe = 4;        // empty parities: stage2 fresh -> starts at 1
    int sc2 = 0, sp = 2;
    for (int t = 0; t < NCHUNK; t++) {
        if (t + 2 < NCHUNK) {
            mbar_wait(barsA + (NSTAGE + sp) * 8, (pe >> sp) & 1);
            pe ^= 1u << sp;
            produce(t + 2, sp);
            sp = (sp == 2) ? 0 : sp + 1;
        }
        mbar_wait(barsA + sc2 * 8, (pf >> sc2) & 1);
        pf ^= 1u << sc2;
        compute(sc2);
        mbar_arrive(barsA + (NSTAGE + sc2) * 8);
        sc2 = (sc2 == 2) ? 0 : sc2 + 1;
    }

    // ---- epilogue ----
    #pragma unroll
    for (int im = 0; im < 2; im++) {
        const int row = m0 + wm * 32 + im * 16 + (lane >> 2);
        #pragma unroll
        for (int jn = 0; jn < 8; jn++) {
            const int col = n0 + wn * 64 + jn * 8 + (lane & 3) * 2;
            const float b0 = bias[col], b1 = bias[col + 1];
            const float* c = acc[im][jn];
            if (row < M)
                *reinterpret_cast<float2*>(out + (size_t)row * NDIM + col) =
                    make_float2(c[0] + b0, c[1] + b1);
            if (row + 8 < M)
                *reinterpret_cast<float2*>(out + (size_t)(row + 8) * NDIM + col) =
                    make_float2(c[2] + b0, c[3] + b1);
        }
    }
}

extern "C" void kernel_launch(void* const* d_in, const int* in_sizes, int n_in,
                              void* d_out, int out_size)
{
    const float* x    = (const float*)d_in[0];
    const int*   qw   = (const int*)  d_in[1];
    const int*   qz   = (const int*)  d_in[2];
    const float* sc   = (const float*)d_in[3];
    const float* bias = (const float*)d_in[4];
    float*       out  = (float*)d_out;

    int M = in_sizes[0] / KDIM;
    if (M > MAXM) M = MAXM;

    cvt_x<<<(MAXM * KDIM / 8 + 255) / 256, 256>>>(x, M);

    cudaFuncSetAttribute(qlin_f16, cudaFuncAttributeMaxDynamicSharedMemorySize, SMEM_DYN);
    dim3 grid(NDIM / BN, (M + BM - 1) / BM);
    qlin_f16<<<grid, 256, SMEM_DYN>>>(qw, qz, sc, bias, out, M);
}

// round 8
// speedup vs baseline: 1.1701x; 1.1701x over previous
#include <cuda_runtime.h>
#include <cuda_fp16.h>
#include <cstdint>

// out[M,11008] = x[M,4096] @ dequant(qweight) + bias
// fp16 mma.sync.m16n8k16 + ldmatrix + cp.async 3-stage; 4 warps @ 64x64 tiles.

#define KDIM    4096
#define NDIM    11008
#define NPACK   1376
#define BM      128
#define BN      128
#define BK      64
#define NCHUNK  64
#define MAXM    2048
#define NTHREADS 128
#define A_STAGE 16384                  // 128 rows x 64 fp16 (128B rows, SW128)
#define B_STAGE 16384                  // 2 subtiles [64k][64n] fp16 (8KB each)
#define SMEM_DYN (3*A_STAGE + 2*B_STAGE + 1024)

__device__ __half x16g[(size_t)MAXM * KDIM];

__device__ __forceinline__ uint32_t smem_u32(const void* p) {
    uint32_t a;
    asm("{ .reg .u64 t; cvta.to.shared.u64 t, %1; cvt.u32.u64 %0, t; }" : "=r"(a) : "l"(p));
    return a;
}
__device__ __forceinline__ uint32_t sw128(uint32_t o) { return o ^ ((o >> 3) & 0x70); }

#define LDSM_X4(r0,r1,r2,r3,addr) \
    asm volatile("ldmatrix.sync.aligned.m8n8.x4.shared.b16 {%0,%1,%2,%3}, [%4];" \
        : "=r"(r0),"=r"(r1),"=r"(r2),"=r"(r3) : "r"(addr))
#define LDSM_X4_T(r0,r1,r2,r3,addr) \
    asm volatile("ldmatrix.sync.aligned.m8n8.x4.trans.shared.b16 {%0,%1,%2,%3}, [%4];" \
        : "=r"(r0),"=r"(r1),"=r"(r2),"=r"(r3) : "r"(addr))

__device__ __forceinline__ void mma16816(float* d, const uint32_t* a,
                                         uint32_t b0, uint32_t b1) {
    asm volatile(
        "mma.sync.aligned.m16n8k16.row.col.f32.f16.f16.f32 "
        "{%0,%1,%2,%3}, {%4,%5,%6,%7}, {%8,%9}, {%0,%1,%2,%3};"
        : "+f"(d[0]), "+f"(d[1]), "+f"(d[2]), "+f"(d[3])
        : "r"(a[0]), "r"(a[1]), "r"(a[2]), "r"(a[3]), "r"(b0), "r"(b1));
}
__device__ __forceinline__ void cp16(uint32_t saddr, const void* g) {
    asm volatile("cp.async.cg.shared.global [%0], [%1], 16;" :: "r"(saddr), "l"(g));
}

// ---------------- prepass: x fp32 -> fp16 (rows >= M zero-filled) ----------------
__global__ __launch_bounds__(256) void cvt_x(const float* __restrict__ x, int M) {
    const size_t e = ((size_t)blockIdx.x * 256 + threadIdx.x) * 8;
    if (e >= (size_t)MAXM * KDIM) return;
    const int row = (int)(e >> 12);
    uint4 v;
    if (row < M) {
        const float4 f0 = reinterpret_cast<const float4*>(x + e)[0];
        const float4 f1 = reinterpret_cast<const float4*>(x + e)[1];
        __half2 p0 = __floats2half2_rn(f0.x, f0.y);
        __half2 p1 = __floats2half2_rn(f0.z, f0.w);
        __half2 p2 = __floats2half2_rn(f1.x, f1.y);
        __half2 p3 = __floats2half2_rn(f1.z, f1.w);
        v.x = *reinterpret_cast<uint32_t*>(&p0);
        v.y = *reinterpret_cast<uint32_t*>(&p1);
        v.z = *reinterpret_cast<uint32_t*>(&p2);
        v.w = *reinterpret_cast<uint32_t*>(&p3);
    } else v = make_uint4(0, 0, 0, 0);
    *reinterpret_cast<uint4*>(x16g + e) = v;
}

// ---------------- main GEMM: 128 threads, 4 warps, 64x64 warp tiles ----------------
__global__ __launch_bounds__(NTHREADS, 2) void qlin_f16(
    const int*   __restrict__ qw,
    const int*   __restrict__ qz,
    const float* __restrict__ sc,
    const float* __restrict__ bias,
    float*       __restrict__ out,
    int M)
{
    extern __shared__ char smem_raw[];
    const uint32_t sb = (smem_u32(smem_raw) + 1023) & ~1023u;
    const uint32_t sA[3] = { sb, sb + A_STAGE, sb + 2 * A_STAGE };
    const uint32_t sB[2] = { sb + 3 * A_STAGE, sb + 3 * A_STAGE + B_STAGE };

    const int tid  = threadIdx.x;
    const int lane = tid & 31;
    const int wid  = tid >> 5;          // 0..3
    const int wm   = wid >> 1;          // 0..1 -> 64-row slice
    const int wn   = wid & 1;           // 0..1 -> 64-col slice
    const int m0   = blockIdx.y * BM;
    const int n0   = blockIdx.x * BN;

    float acc[4][8][4];
    #pragma unroll
    for (int im = 0; im < 4; im++)
        #pragma unroll
        for (int jn = 0; jn < 8; jn++)
            #pragma unroll
            for (int r = 0; r < 4; r++) acc[im][jn][r] = 0.f;

    // ---- A cp.async coords: 1024 16B chunks, 8 per thread ----
    auto cpA = [&](int t, int stg) {
        const __half* src = x16g + (size_t)m0 * KDIM + t * BK;
        #pragma unroll
        for (int p = 0; p < 8; p++) {
            const int c   = tid + p * NTHREADS;
            const int row = c >> 3, kc = c & 7;
            cp16(sA[stg] + sw128((uint32_t)(row * 128 + kc * 16)),
                 src + (size_t)row * KDIM + kc * 8);
        }
        asm volatile("cp.async.commit_group;");
    };

    // ---- B dequant coords: 16 packed cols x 8 k-rows base ----
    const int nb = tid & 15;            // packed col (8 n each)
    const int kq = tid >> 4;            // 0..7
    const size_t nbG = (size_t)(n0 >> 3) + nb;
    __half2 zc[4], s2[4];
    int qreg[8];

    auto refresh_group = [&](int g) {
        const uint32_t zq = (uint32_t)qz[(size_t)g * NPACK + nbG];
        #pragma unroll
        for (int j = 0; j < 4; j++) {
            uint32_t p = ((zq >> (4 * j)) & 0x000F000Fu) | 0x64006400u;
            zc[j] = *reinterpret_cast<__half2*>(&p);
        }
        const float4* sp = reinterpret_cast<const float4*>(
            sc + (size_t)g * NDIM + n0 + nb * 8);
        const float4 sa = sp[0], sbv = sp[1];
        s2[0] = __floats2half2_rn(sa.x, sbv.x);
        s2[1] = __floats2half2_rn(sa.y, sbv.y);
        s2[2] = __floats2half2_rn(sa.z, sbv.z);
        s2[3] = __floats2half2_rn(sa.w, sbv.w);
    };
    auto ldgQ = [&](int t) {
        #pragma unroll
        for (int i = 0; i < 8; i++)
            qreg[i] = qw[(size_t)(t * BK + kq + 8 * i) * NPACK + nbG];
    };
    auto dequantB = [&](int stg) {
        char* Bsub = smem_raw + (sB[stg] - smem_u32(smem_raw)) + (nb >> 3) * 8192;
        const uint32_t cb = (uint32_t)((nb & 7) * 16);
        #pragma unroll
        for (int i = 0; i < 8; i++) {
            const int k = kq + 8 * i;
            const uint32_t q = (uint32_t)qreg[i];
            uint32_t w[4];
            #pragma unroll
            for (int j = 0; j < 4; j++) {
                uint32_t p = ((q >> (4 * j)) & 0x000F000Fu) | 0x64006400u;
                __half2 hv = __hmul2(__hsub2(*reinterpret_cast<__half2*>(&p), zc[j]), s2[j]);
                w[j] = *reinterpret_cast<uint32_t*>(&hv);
            }
            uint4 v;   // pair reorder -> n0..n7 memory order
            v.x = __byte_perm(w[0], w[1], 0x5410);
            v.y = __byte_perm(w[2], w[3], 0x5410);
            v.z = __byte_perm(w[0], w[1], 0x7632);
            v.w = __byte_perm(w[2], w[3], 0x7632);
            *reinterpret_cast<uint4*>(Bsub + sw128((uint32_t)(k * 128) + cb)) = v;
        }
    };

    // ---- compute one BK=64 chunk ----
    const int lr = lane & 15, lc = lane >> 4;
    auto compute = [&](int aStg, int bStg) {
        const uint32_t aB = sA[aStg];
        const uint32_t bB = sB[bStg] + wn * 8192;
        #pragma unroll
        for (int ks = 0; ks < 4; ks++) {
            uint32_t a[4][4];
            #pragma unroll
            for (int im = 0; im < 4; im++) {
                const uint32_t addr = aB + sw128(
                    (uint32_t)((wm * 64 + im * 16 + lr) * 128 + ks * 32 + lc * 16));
                LDSM_X4(a[im][0], a[im][1], a[im][2], a[im][3], addr);
            }
            #pragma unroll
            for (int jn = 0; jn < 4; jn++) {
                uint32_t b0, b1, b2, b3;
                const uint32_t addr = bB + sw128(
                    (uint32_t)((ks * 16 + lr) * 128 + jn * 32 + lc * 16));
                LDSM_X4_T(b0, b1, b2, b3, addr);
                #pragma unroll
                for (int im = 0; im < 4; im++) {
                    mma16816(acc[im][2 * jn],     a[im], b0, b1);
                    mma16816(acc[im][2 * jn + 1], a[im], b2, b3);
                }
            }
        }
    };

    // ---- prologue ----
    ldgQ(0);
    cpA(0, 0);
    cpA(1, 1);
    refresh_group(0);
    dequantB(0);
    ldgQ(1);
    asm volatile("cp.async.wait_group 1;");
    __syncthreads();

    // ---- main loop ----
    for (int t = 0; t < NCHUNK; t++) {
        compute(t % 3, t & 1);
        if (t + 2 < NCHUNK) cpA(t + 2, (t + 2) % 3);
        if (t + 1 < NCHUNK) {
            if (((t + 1) & 1) == 0) refresh_group((t + 1) >> 1);
            dequantB((t + 1) & 1);
            if (t + 2 < NCHUNK) ldgQ(t + 2);
            asm volatile("cp.async.wait_group 1;");
            __syncthreads();
        }
    }

    // ---- epilogue ----
    #pragma unroll
    for (int im = 0; im < 4; im++) {
        const int row = m0 + wm * 64 + im * 16 + (lane >> 2);
        #pragma unroll
        for (int jn = 0; jn < 8; jn++) {
            const int col = n0 + wn * 64 + jn * 8 + (lane & 3) * 2;
            const float b0 = bias[col], b1 = bias[col + 1];
            const float* c = acc[im][jn];
            if (row < M)
                *reinterpret_cast<float2*>(out + (size_t)row * NDIM + col) =
                    make_float2(c[0] + b0, c[1] + b1);
            if (row + 8 < M)
                *reinterpret_cast<float2*>(out + (size_t)(row + 8) * NDIM + col) =
                    make_float2(c[2] + b0, c[3] + b1);
        }
    }
}

extern "C" void kernel_launch(void* const* d_in, const int* in_sizes, int n_in,
                              void* d_out, int out_size)
{
    const float* x    = (const float*)d_in[0];
    const int*   qw   = (const int*)  d_in[1];
    const int*   qz   = (const int*)  d_in[2];
    const float* sc   = (const float*)d_in[3];
    const float* bias = (const float*)d_in[4];
    float*       out  = (float*)d_out;

    int M = in_sizes[0] / KDIM;
    if (M > MAXM) M = MAXM;

    cvt_x<<<(MAXM * KDIM / 8 + 255) / 256, 256>>>(x, M);

    cudaFuncSetAttribute(qlin_f16, cudaFuncAttributeMaxDynamicSharedMemorySize, SMEM_DYN);
    dim3 grid(NDIM / BN, (M + BM - 1) / BM);
    qlin_f16<<<grid, NTHREADS, SMEM_DYN>>>(qw, qz, sc, bias, out, M);
}

// round 10
// speedup vs baseline: 1.4890x; 1.2726x over previous
#include <cuda_runtime.h>
#include <cuda_fp16.h>
#include <cstdint>

// out[M,11008] = x[M,4096] @ dequant(qweight) + bias
// Warp-specialized: 8 consumer warps (mma/ldmatrix) + 4 producer warps
// (cp.async A, int4->fp16 dequant B). 6-stage smem ring, named barriers.

#define KDIM    4096
#define NDIM    11008
#define NPACK   1376
#define BM      128
#define BN      128
#define BK      64
#define NCHUNK  64
#define MAXM    2048
#define NTHREADS 384                 // 256 consumers + 128 producers
#define A_BYTES 16384                // 128 rows x 64 fp16 (128B rows, SW128)
#define B_BYTES 16384                // 2 subtiles [64k][64n] fp16
#define STAGE   (A_BYTES + B_BYTES)  // 32768
#define NSTAGE  6
#define SMEM_DYN (NSTAGE*STAGE + 1024)   // 197632

// named barrier ids: FULL 1..6, EMPTY 7..12
#define BAR_FULL(s)  (1 + (s))
#define BAR_EMPTY(s) (1 + NSTAGE + (s))

__device__ __half x16g[(size_t)MAXM * KDIM];

__device__ __forceinline__ uint32_t smem_u32(const void* p) {
    uint32_t a;
    asm("{ .reg .u64 t; cvta.to.shared.u64 t, %1; cvt.u32.u64 %0, t; }" : "=r"(a) : "l"(p));
    return a;
}
__device__ __forceinline__ uint32_t sw128(uint32_t o) { return o ^ ((o >> 3) & 0x70); }
__device__ __forceinline__ void bar_sync(int id) {
    asm volatile("bar.sync %0, %1;" :: "r"(id), "n"(NTHREADS) : "memory");
}
__device__ __forceinline__ void bar_arrive(int id) {
    asm volatile("bar.arrive %0, %1;" :: "r"(id), "n"(NTHREADS) : "memory");
}

#define LDSM_X4(r0,r1,r2,r3,addr) \
    asm volatile("ldmatrix.sync.aligned.m8n8.x4.shared.b16 {%0,%1,%2,%3}, [%4];" \
        : "=r"(r0),"=r"(r1),"=r"(r2),"=r"(r3) : "r"(addr))
#define LDSM_X4_T(r0,r1,r2,r3,addr) \
    asm volatile("ldmatrix.sync.aligned.m8n8.x4.trans.shared.b16 {%0,%1,%2,%3}, [%4];" \
        : "=r"(r0),"=r"(r1),"=r"(r2),"=r"(r3) : "r"(addr))

__device__ __forceinline__ void mma16816(float* d, const uint32_t* a,
                                         uint32_t b0, uint32_t b1) {
    asm volatile(
        "mma.sync.aligned.m16n8k16.row.col.f32.f16.f16.f32 "
        "{%0,%1,%2,%3}, {%4,%5,%6,%7}, {%8,%9}, {%0,%1,%2,%3};"
        : "+f"(d[0]), "+f"(d[1]), "+f"(d[2]), "+f"(d[3])
        : "r"(a[0]), "r"(a[1]), "r"(a[2]), "r"(a[3]), "r"(b0), "r"(b1));
}
__device__ __forceinline__ void cp16(uint32_t saddr, const void* g) {
    asm volatile("cp.async.cg.shared.global [%0], [%1], 16;" :: "r"(saddr), "l"(g));
}

// ---------------- prepass: x fp32 -> fp16 (rows >= M zero-filled) ----------------
__global__ __launch_bounds__(256) void cvt_x(const float* __restrict__ x, int M) {
    const size_t e = ((size_t)blockIdx.x * 256 + threadIdx.x) * 8;
    if (e >= (size_t)MAXM * KDIM) return;
    const int row = (int)(e >> 12);
    uint4 v;
    if (row < M) {
        const float4 f0 = reinterpret_cast<const float4*>(x + e)[0];
        const float4 f1 = reinterpret_cast<const float4*>(x + e)[1];
        __half2 p0 = __floats2half2_rn(f0.x, f0.y);
        __half2 p1 = __floats2half2_rn(f0.z, f0.w);
        __half2 p2 = __floats2half2_rn(f1.x, f1.y);
        __half2 p3 = __floats2half2_rn(f1.z, f1.w);
        v.x = *reinterpret_cast<uint32_t*>(&p0);
        v.y = *reinterpret_cast<uint32_t*>(&p1);
        v.z = *reinterpret_cast<uint32_t*>(&p2);
        v.w = *reinterpret_cast<uint32_t*>(&p3);
    } else v = make_uint4(0, 0, 0, 0);
    *reinterpret_cast<uint4*>(x16g + e) = v;
}

// ---------------- main GEMM ----------------
__global__ __launch_bounds__(NTHREADS, 1) void qlin_f16(
    const int*   __restrict__ qw,
    const int*   __restrict__ qz,
    const float* __restrict__ sc,
    const float* __restrict__ bias,
    float*       __restrict__ out,
    int M)
{
    extern __shared__ char smem_raw[];
    const uint32_t sb0 = smem_u32(smem_raw);
    const uint32_t sb  = (sb0 + 1023) & ~1023u;

    const int tid  = threadIdx.x;
    const int lane = tid & 31;
    const int wid  = tid >> 5;          // 0..11
    const int m0   = blockIdx.y * BM;
    const int n0   = blockIdx.x * BN;

    if (wid >= 8) {
        // ================= PRODUCER (warps 8..11, 128 threads) =================
        const int ptid = tid - 256;     // 0..127
        const int nb   = ptid & 15;     // packed col (8 n each)
        const int kq   = ptid >> 4;     // 0..7
        const size_t nbG = (size_t)(n0 >> 3) + nb;

        __half2 zc[4], s2[4];
        int qcur[8], qnxt[8];

        auto refresh_group = [&](int g) {
            const uint32_t zq = (uint32_t)qz[(size_t)g * NPACK + nbG];
            #pragma unroll
            for (int j = 0; j < 4; j++) {
                uint32_t p = ((zq >> (4 * j)) & 0x000F000Fu) | 0x64006400u;
                zc[j] = *reinterpret_cast<__half2*>(&p);
            }
            const float4* sp = reinterpret_cast<const float4*>(
                sc + (size_t)g * NDIM + n0 + nb * 8);
            const float4 sa = sp[0], sbv = sp[1];
            s2[0] = __floats2half2_rn(sa.x, sbv.x);
            s2[1] = __floats2half2_rn(sa.y, sbv.y);
            s2[2] = __floats2half2_rn(sa.z, sbv.z);
            s2[3] = __floats2half2_rn(sa.w, sbv.w);
        };
        auto ldgQ = [&](int t, int* q) {
            #pragma unroll
            for (int i = 0; i < 8; i++)
                q[i] = qw[(size_t)(t * BK + kq + 8 * i) * NPACK + nbG];
        };

        ldgQ(0, qcur);
        refresh_group(0);

        for (int t = 0; t < NCHUNK; t++) {
            const int s = t % NSTAGE;
            const uint32_t stg = sb + s * STAGE;
            if (t >= NSTAGE) bar_sync(BAR_EMPTY(s));

            // A: 8 cp.async x 16B per producer thread
            {
                const __half* src = x16g + (size_t)m0 * KDIM + t * BK;
                #pragma unroll
                for (int p = 0; p < 8; p++) {
                    const int c = ptid + p * 128;
                    const int row = c >> 3, kc = c & 7;
                    cp16(stg + sw128((uint32_t)(row * 128 + kc * 16)),
                         src + (size_t)row * KDIM + kc * 8);
                }
                asm volatile("cp.async.commit_group;");
            }
            if (t + 1 < NCHUNK) ldgQ(t + 1, qnxt);     // overlap LDG w/ dequant

            // B dequant -> STS (8 int32 per thread)
            {
                char* Bsub = smem_raw + (stg + A_BYTES - sb0) + (nb >> 3) * 8192;
                const uint32_t cb = (uint32_t)((nb & 7) * 16);
                #pragma unroll
                for (int i = 0; i < 8; i++) {
                    const int k = kq + 8 * i;
                    const uint32_t q = (uint32_t)qcur[i];
                    uint32_t w[4];
                    #pragma unroll
                    for (int j = 0; j < 4; j++) {
                        uint32_t p = ((q >> (4 * j)) & 0x000F000Fu) | 0x64006400u;
                        __half2 hv = __hmul2(
                            __hsub2(*reinterpret_cast<__half2*>(&p), zc[j]), s2[j]);
                        w[j] = *reinterpret_cast<uint32_t*>(&hv);
                    }
                    uint4 v;   // pair reorder -> n0..n7 memory order
                    v.x = __byte_perm(w[0], w[1], 0x5410);
                    v.y = __byte_perm(w[2], w[3], 0x5410);
                    v.z = __byte_perm(w[0], w[1], 0x7632);
                    v.w = __byte_perm(w[2], w[3], 0x7632);
                    *reinterpret_cast<uint4*>(Bsub + sw128((uint32_t)(k * 128) + cb)) = v;
                }
            }

            asm volatile("cp.async.wait_group 0;");   // A(t) landed
            asm volatile("membar.cta;");              // STS + cp visible CTA-wide
            bar_arrive(BAR_FULL(s));

            #pragma unroll
            for (int i = 0; i < 8; i++) qcur[i] = qnxt[i];
            if ((t & 1) && (t + 1 < NCHUNK)) refresh_group((t + 1) >> 1);
        }
        return;   // producers done; no further CTA-wide syncs exist
    }

    // ================= CONSUMER (warps 0..7) =================
    const int wm = wid >> 1;            // 0..3 -> 32-row slice
    const int wn = wid & 1;             // 0..1 -> 64-col slice

    float acc[2][8][4];
    #pragma unroll
    for (int im = 0; im < 2; im++)
        #pragma unroll
        for (int jn = 0; jn < 8; jn++)
            #pragma unroll
            for (int r = 0; r < 4; r++) acc[im][jn][r] = 0.f;

    const int lr = lane & 15, lc = lane >> 4;

    for (int t = 0; t < NCHUNK; t++) {
        const int s = t % NSTAGE;
        bar_sync(BAR_FULL(s));
        const uint32_t aB = sb + s * STAGE;
        const uint32_t bB = aB + A_BYTES + wn * 8192;
        #pragma unroll
        for (int ks = 0; ks < 4; ks++) {
            uint32_t a[2][4];
            #pragma unroll
            for (int im = 0; im < 2; im++) {
                const uint32_t addr = aB + sw128(
                    (uint32_t)((wm * 32 + im * 16 + lr) * 128 + ks * 32 + lc * 16));
                LDSM_X4(a[im][0], a[im][1], a[im][2], a[im][3], addr);
            }
            #pragma unroll
            for (int jn = 0; jn < 4; jn++) {
                uint32_t b0, b1, b2, b3;
                const uint32_t addr = bB + sw128(
                    (uint32_t)((ks * 16 + lr) * 128 + jn * 32 + lc * 16));
                LDSM_X4_T(b0, b1, b2, b3, addr);
                #pragma unroll
                for (int im = 0; im < 2; im++) {
                    mma16816(acc[im][2 * jn],     a[im], b0, b1);
                    mma16816(acc[im][2 * jn + 1], a[im], b2, b3);
                }
            }
        }
        bar_arrive(BAR_EMPTY(s));
    }

    // ---- epilogue (consumers only) ----
    #pragma unroll
    for (int im = 0; im < 2; im++) {
        const int row = m0 + wm * 32 + im * 16 + (lane >> 2);
        #pragma unroll
        for (int jn = 0; jn < 8; jn++) {
            const int col = n0 + wn * 64 + jn * 8 + (lane & 3) * 2;
            const float b0 = bias[col], b1 = bias[col + 1];
            const float* c = acc[im][jn];
            if (row < M)
                *reinterpret_cast<float2*>(out + (size_t)row * NDIM + col) =
                    make_float2(c[0] + b0, c[1] + b1);
            if (row + 8 < M)
                *reinterpret_cast<float2*>(out + (size_t)(row + 8) * NDIM + col) =
                    make_float2(c[2] + b0, c[3] + b1);
        }
    }
}

extern "C" void kernel_launch(void* const* d_in, const int* in_sizes, int n_in,
                              void* d_out, int out_size)
{
    const float* x    = (const float*)d_in[0];
    const int*   qw   = (const int*)  d_in[1];
    const int*   qz   = (const int*)  d_in[2];
    const float* sc   = (const float*)d_in[3];
    const float* bias = (const float*)d_in[4];
    float*       out  = (float*)d_out;

    int M = in_sizes[0] / KDIM;
    if (M > MAXM) M = MAXM;

    cvt_x<<<(MAXM * KDIM / 8 + 255) / 256, 256>>>(x, M);

    cudaFuncSetAttribute(qlin_f16, cudaFuncAttributeMaxDynamicSharedMemorySize, SMEM_DYN);
    dim3 grid(NDIM / BN, (M + BM - 1) / BM);
    qlin_f16<<<grid, NTHREADS, SMEM_DYN>>>(qw, qz, sc, bias, out, M);
}

// round 11
// speedup vs baseline: 1.5020x; 1.0087x over previous
#include <cuda_runtime.h>
#include <cuda_fp16.h>
#include <cstdint>

// out[M,11008] = x[M,4096] @ dequant(qweight) + bias
// Warp-specialized 8+8: 8 consumer warps (ldmatrix/mma, 32x64 tiles) +
// 8 producer warps (cp.async A, int4->fp16 dequant B). 6-stage ring,
// named barriers. 512 threads, 1 CTA/SM, 16 warps/SM.

#define KDIM    4096
#define NDIM    11008
#define NPACK   1376
#define BM      128
#define BN      128
#define BK      64
#define NCHUNK  64
#define MAXM    2048
#define NTHREADS 512                 // 256 consumers + 256 producers
#define A_BYTES 16384                // 128 rows x 64 fp16 (128B rows, SW128)
#define B_BYTES 16384                // 2 subtiles [64k][64n] fp16
#define STAGE   (A_BYTES + B_BYTES)  // 32768
#define NSTAGE  6
#define SMEM_DYN (NSTAGE*STAGE + 1024)   // 197632

// named barrier ids: FULL 1..6, EMPTY 7..12
#define BAR_FULL(s)  (1 + (s))
#define BAR_EMPTY(s) (1 + NSTAGE + (s))

__device__ __half x16g[(size_t)MAXM * KDIM];

__device__ __forceinline__ uint32_t smem_u32(const void* p) {
    uint32_t a;
    asm("{ .reg .u64 t; cvta.to.shared.u64 t, %1; cvt.u32.u64 %0, t; }" : "=r"(a) : "l"(p));
    return a;
}
__device__ __forceinline__ uint32_t sw128(uint32_t o) { return o ^ ((o >> 3) & 0x70); }
__device__ __forceinline__ void bar_sync(int id) {
    asm volatile("bar.sync %0, %1;" :: "r"(id), "n"(NTHREADS) : "memory");
}
__device__ __forceinline__ void bar_arrive(int id) {
    asm volatile("bar.arrive %0, %1;" :: "r"(id), "n"(NTHREADS) : "memory");
}

#define LDSM_X4(r0,r1,r2,r3,addr) \
    asm volatile("ldmatrix.sync.aligned.m8n8.x4.shared.b16 {%0,%1,%2,%3}, [%4];" \
        : "=r"(r0),"=r"(r1),"=r"(r2),"=r"(r3) : "r"(addr))
#define LDSM_X4_T(r0,r1,r2,r3,addr) \
    asm volatile("ldmatrix.sync.aligned.m8n8.x4.trans.shared.b16 {%0,%1,%2,%3}, [%4];" \
        : "=r"(r0),"=r"(r1),"=r"(r2),"=r"(r3) : "r"(addr))

__device__ __forceinline__ void mma16816(float* d, const uint32_t* a,
                                         uint32_t b0, uint32_t b1) {
    asm volatile(
        "mma.sync.aligned.m16n8k16.row.col.f32.f16.f16.f32 "
        "{%0,%1,%2,%3}, {%4,%5,%6,%7}, {%8,%9}, {%0,%1,%2,%3};"
        : "+f"(d[0]), "+f"(d[1]), "+f"(d[2]), "+f"(d[3])
        : "r"(a[0]), "r"(a[1]), "r"(a[2]), "r"(a[3]), "r"(b0), "r"(b1));
}
__device__ __forceinline__ void cp16(uint32_t saddr, const void* g) {
    asm volatile("cp.async.cg.shared.global [%0], [%1], 16;" :: "r"(saddr), "l"(g));
}

// ---------------- prepass: x fp32 -> fp16 (rows >= M zero-filled) ----------------
__global__ __launch_bounds__(256) void cvt_x(const float* __restrict__ x, int M) {
    const size_t e = ((size_t)blockIdx.x * 256 + threadIdx.x) * 8;
    if (e >= (size_t)MAXM * KDIM) return;
    const int row = (int)(e >> 12);
    uint4 v;
    if (row < M) {
        const float4 f0 = reinterpret_cast<const float4*>(x + e)[0];
        const float4 f1 = reinterpret_cast<const float4*>(x + e)[1];
        __half2 p0 = __floats2half2_rn(f0.x, f0.y);
        __half2 p1 = __floats2half2_rn(f0.z, f0.w);
        __half2 p2 = __floats2half2_rn(f1.x, f1.y);
        __half2 p3 = __floats2half2_rn(f1.z, f1.w);
        v.x = *reinterpret_cast<uint32_t*>(&p0);
        v.y = *reinterpret_cast<uint32_t*>(&p1);
        v.z = *reinterpret_cast<uint32_t*>(&p2);
        v.w = *reinterpret_cast<uint32_t*>(&p3);
    } else v = make_uint4(0, 0, 0, 0);
    *reinterpret_cast<uint4*>(x16g + e) = v;
}

// ---------------- main GEMM ----------------
__global__ __launch_bounds__(NTHREADS, 1) void qlin_f16(
    const int*   __restrict__ qw,
    const int*   __restrict__ qz,
    const float* __restrict__ sc,
    const float* __restrict__ bias,
    float*       __restrict__ out,
    int M)
{
    extern __shared__ char smem_raw[];
    const uint32_t sb0 = smem_u32(smem_raw);
    const uint32_t sb  = (sb0 + 1023) & ~1023u;

    const int tid  = threadIdx.x;
    const int lane = tid & 31;
    const int wid  = tid >> 5;          // 0..15
    const int m0   = blockIdx.y * BM;
    const int n0   = blockIdx.x * BN;

    if (wid >= 8) {
        // ================= PRODUCER (warps 8..15, 256 threads) =================
        const int ptid = tid - 256;     // 0..255
        const int nb   = ptid & 15;     // packed col (8 n each)
        const int kq   = ptid >> 4;     // 0..15
        const size_t nbG = (size_t)(n0 >> 3) + nb;

        __half2 zc[4], s2[4];
        int qcur[4], qnxt[4];

        auto refresh_group = [&](int g) {
            const uint32_t zq = (uint32_t)qz[(size_t)g * NPACK + nbG];
            #pragma unroll
            for (int j = 0; j < 4; j++) {
                uint32_t p = ((zq >> (4 * j)) & 0x000F000Fu) | 0x64006400u;
                zc[j] = *reinterpret_cast<__half2*>(&p);
            }
            const float4* sp = reinterpret_cast<const float4*>(
                sc + (size_t)g * NDIM + n0 + nb * 8);
            const float4 sa = sp[0], sbv = sp[1];
            s2[0] = __floats2half2_rn(sa.x, sbv.x);
            s2[1] = __floats2half2_rn(sa.y, sbv.y);
            s2[2] = __floats2half2_rn(sa.z, sbv.z);
            s2[3] = __floats2half2_rn(sa.w, sbv.w);
        };
        auto ldgQ = [&](int t, int* q) {
            #pragma unroll
            for (int i = 0; i < 4; i++)
                q[i] = qw[(size_t)(t * BK + kq + 16 * i) * NPACK + nbG];
        };

        ldgQ(0, qcur);
        refresh_group(0);

        for (int t = 0; t < NCHUNK; t++) {
            const int s = t % NSTAGE;
            const uint32_t stg = sb + s * STAGE;
            if (t >= NSTAGE) bar_sync(BAR_EMPTY(s));

            // A: 4 cp.async x 16B per producer thread (1024 lines total)
            {
                const __half* src = x16g + (size_t)m0 * KDIM + t * BK;
                #pragma unroll
                for (int p = 0; p < 4; p++) {
                    const int c = ptid + p * 256;
                    const int row = c >> 3, kc = c & 7;
                    cp16(stg + sw128((uint32_t)(row * 128 + kc * 16)),
                         src + (size_t)row * KDIM + kc * 8);
                }
                asm volatile("cp.async.commit_group;");
            }
            if (t + 1 < NCHUNK) ldgQ(t + 1, qnxt);     // overlap LDG w/ dequant

            // B dequant -> STS (4 int32 per thread)
            {
                char* Bsub = smem_raw + (stg + A_BYTES - sb0) + (nb >> 3) * 8192;
                const uint32_t cb = (uint32_t)((nb & 7) * 16);
                #pragma unroll
                for (int i = 0; i < 4; i++) {
                    const int k = kq + 16 * i;
                    const uint32_t q = (uint32_t)qcur[i];
                    uint32_t w[4];
                    #pragma unroll
                    for (int j = 0; j < 4; j++) {
                        uint32_t p = ((q >> (4 * j)) & 0x000F000Fu) | 0x64006400u;
                        __half2 hv = __hmul2(
                            __hsub2(*reinterpret_cast<__half2*>(&p), zc[j]), s2[j]);
                        w[j] = *reinterpret_cast<uint32_t*>(&hv);
                    }
                    uint4 v;   // pair reorder -> n0..n7 memory order
                    v.x = __byte_perm(w[0], w[1], 0x5410);
                    v.y = __byte_perm(w[2], w[3], 0x5410);
                    v.z = __byte_perm(w[0], w[1], 0x7632);
                    v.w = __byte_perm(w[2], w[3], 0x7632);
                    *reinterpret_cast<uint4*>(Bsub + sw128((uint32_t)(k * 128) + cb)) = v;
                }
            }

            asm volatile("cp.async.wait_group 0;");   // A(t) landed
            asm volatile("membar.cta;");              // STS + cp visible CTA-wide
            bar_arrive(BAR_FULL(s));

            #pragma unroll
            for (int i = 0; i < 4; i++) qcur[i] = qnxt[i];
            if ((t & 1) && (t + 1 < NCHUNK)) refresh_group((t + 1) >> 1);
        }
        return;   // producers done
    }

    // ================= CONSUMER (warps 0..7) =================
    const int wm = wid >> 1;            // 0..3 -> 32-row slice
    const int wn = wid & 1;             // 0..1 -> 64-col slice

    float acc[2][8][4];
    #pragma unroll
    for (int im = 0; im < 2; im++)
        #pragma unroll
        for (int jn = 0; jn < 8; jn++)
            #pragma unroll
            for (int r = 0; r < 4; r++) acc[im][jn][r] = 0.f;

    const int lr = lane & 15, lc = lane >> 4;

    for (int t = 0; t < NCHUNK; t++) {
        const int s = t % NSTAGE;
        bar_sync(BAR_FULL(s));
        const uint32_t aB = sb + s * STAGE;
        const uint32_t bB = aB + A_BYTES + wn * 8192;
        #pragma unroll
        for (int ks = 0; ks < 4; ks++) {
            uint32_t a[2][4];
            #pragma unroll
            for (int im = 0; im < 2; im++) {
                const uint32_t addr = aB + sw128(
                    (uint32_t)((wm * 32 + im * 16 + lr) * 128 + ks * 32 + lc * 16));
                LDSM_X4(a[im][0], a[im][1], a[im][2], a[im][3], addr);
            }
            #pragma unroll
            for (int jn = 0; jn < 4; jn++) {
                uint32_t b0, b1, b2, b3;
                const uint32_t addr = bB + sw128(
                    (uint32_t)((ks * 16 + lr) * 128 + jn * 32 + lc * 16));
                LDSM_X4_T(b0, b1, b2, b3, addr);
                #pragma unroll
                for (int im = 0; im < 2; im++) {
                    mma16816(acc[im][2 * jn],     a[im], b0, b1);
                    mma16816(acc[im][2 * jn + 1], a[im], b2, b3);
                }
            }
        }
        bar_arrive(BAR_EMPTY(s));
    }

    // ---- epilogue (consumers only) ----
    #pragma unroll
    for (int im = 0; im < 2; im++) {
        const int row = m0 + wm * 32 + im * 16 + (lane >> 2);
        #pragma unroll
        for (int jn = 0; jn < 8; jn++) {
            const int col = n0 + wn * 64 + jn * 8 + (lane & 3) * 2;
            const float b0 = bias[col], b1 = bias[col + 1];
            const float* c = acc[im][jn];
            if (row < M)
                *reinterpret_cast<float2*>(out + (size_t)row * NDIM + col) =
                    make_float2(c[0] + b0, c[1] + b1);
            if (row + 8 < M)
                *reinterpret_cast<float2*>(out + (size_t)(row + 8) * NDIM + col) =
                    make_float2(c[2] + b0, c[3] + b1);
        }
    }
}

extern "C" void kernel_launch(void* const* d_in, const int* in_sizes, int n_in,
                              void* d_out, int out_size)
{
    const float* x    = (const float*)d_in[0];
    const int*   qw   = (const int*)  d_in[1];
    const int*   qz   = (const int*)  d_in[2];
    const float* sc   = (const float*)d_in[3];
    const float* bias = (const float*)d_in[4];
    float*       out  = (float*)d_out;

    int M = in_sizes[0] / KDIM;
    if (M > MAXM) M = MAXM;

    cvt_x<<<(MAXM * KDIM / 8 + 255) / 256, 256>>>(x, M);

    cudaFuncSetAttribute(qlin_f16, cudaFuncAttributeMaxDynamicSharedMemorySize, SMEM_DYN);
    dim3 grid(NDIM / BN, (M + BM - 1) / BM);
    qlin_f16<<<grid, NTHREADS, SMEM_DYN>>>(qw, qz, sc, bias, out, M);
}